// round 5
// baseline (speedup 1.0000x reference)
#include <cuda_runtime.h>
#include <cuda_fp16.h>
#include <cstdint>

#define B_ 8
#define N_ 2048
#define D_ 128
#define NC 128                // 2048 / 16 k-chunks
#define APITCH 72             // halfs per A k-row (64 j + pad) -> 144B
#define BPITCH 24             // halfs per B d-row (16 k + pad) -> 48B

// ---------------------------------------------------------------------------
// Device scratch (no runtime allocation allowed)
// ---------------------------------------------------------------------------
__device__ float g_S[B_ * N_ * D_];     // un-normalized sum_neighbors (32 MB)
__device__ int   g_deg[B_ * N_];        // nnz per cost row
__device__ float g_Wt[2 * D_ * D_];     // W transposed: Wt[f][d]
__device__ float g_Bt[B_ * D_ * N_];    // emb transposed: Bt[b][d][i] (8 MB)

typedef unsigned long long ull;

// ---------------------------------------------------------------------------
// helpers
// ---------------------------------------------------------------------------
__device__ __forceinline__ void hmma(float* c, const uint32_t* a, const uint32_t* b) {
    asm volatile(
        "mma.sync.aligned.m16n8k16.row.col.f32.f16.f16.f32 "
        "{%0,%1,%2,%3}, {%4,%5,%6,%7}, {%8,%9}, {%0,%1,%2,%3};"
        : "+f"(c[0]), "+f"(c[1]), "+f"(c[2]), "+f"(c[3])
        : "r"(a[0]), "r"(a[1]), "r"(a[2]), "r"(a[3]), "r"(b[0]), "r"(b[1]));
}
__device__ __forceinline__ void ldsm4(uint32_t* r, uint32_t addr) {
    asm volatile("ldmatrix.sync.aligned.m8n8.x4.shared.b16 {%0,%1,%2,%3}, [%4];"
                 : "=r"(r[0]), "=r"(r[1]), "=r"(r[2]), "=r"(r[3]) : "r"(addr));
}
__device__ __forceinline__ void ldsm4t(uint32_t* r, uint32_t addr) {
    asm volatile("ldmatrix.sync.aligned.m8n8.x4.trans.shared.b16 {%0,%1,%2,%3}, [%4];"
                 : "=r"(r[0]), "=r"(r[1]), "=r"(r[2]), "=r"(r[3]) : "r"(addr));
}
__device__ __forceinline__ uint32_t sm_addr(const void* p) {
    return (uint32_t)__cvta_generic_to_shared(p);
}
// exact fp32 -> fp16 hi/lo split of a float4, packed as half2 words
__device__ __forceinline__ void split_f4(float4 v, uint32_t& h0, uint32_t& h1,
                                         uint32_t& l0, uint32_t& l1) {
    __half2 a = __floats2half2_rn(v.x, v.y);
    __half2 b = __floats2half2_rn(v.z, v.w);
    float2 af = __half22float2(a), bf = __half22float2(b);
    __half2 c = __floats2half2_rn(v.x - af.x, v.y - af.y);
    __half2 d = __floats2half2_rn(v.z - bf.x, v.w - bf.y);
    h0 = *(uint32_t*)&a; h1 = *(uint32_t*)&b;
    l0 = *(uint32_t*)&c; l1 = *(uint32_t*)&d;
}
// f32x2 helpers for the SIMT gemm2
__device__ __forceinline__ ull pack2(float lo, float hi) {
    ull r; asm("mov.b64 %0, {%1,%2};" : "=l"(r) : "f"(lo), "f"(hi)); return r;
}
__device__ __forceinline__ void fma2(ull& d, ull a, ull b) {
    asm("fma.rn.f32x2 %0, %1, %2, %3;" : "=l"(d) : "l"(a), "l"(b), "l"(d));
}
__device__ __forceinline__ float2 unpack2(ull v) {
    float2 r; asm("mov.b64 {%0,%1}, %2;" : "=f"(r.x), "=f"(r.y) : "l"(v)); return r;
}

// ---------------------------------------------------------------------------
// prep: zero degree counters, transpose W into Wt[f][d]
// ---------------------------------------------------------------------------
__global__ void prep_kernel(const float* __restrict__ W) {
    int i = blockIdx.x * 256 + threadIdx.x;
    if (i < B_ * N_) g_deg[i] = 0;
    if (i < 2 * D_ * D_) {
        int f = i >> 7, d = i & 127;
        g_Wt[i] = W[d * 2 * D_ + f];
    }
}

// ---------------------------------------------------------------------------
// prep2: transpose emb[b][i][d] -> g_Bt[b][d][i]
// ---------------------------------------------------------------------------
__global__ void prep2_kernel(const float* __restrict__ emb) {
    __shared__ float tile[32][33];
    int b = blockIdx.z;
    int i0 = blockIdx.x * 32;
    int d0 = blockIdx.y * 32;
    int tx = threadIdx.x, ty = threadIdx.y;   // (32, 8)
    const float* eB = emb + (size_t)b * N_ * D_;
    #pragma unroll
    for (int r = 0; r < 32; r += 8)
        tile[ty + r][tx] = eB[(size_t)(i0 + ty + r) * D_ + d0 + tx];
    __syncthreads();
    #pragma unroll
    for (int r = 0; r < 32; r += 8) {
        size_t o = (size_t)b * D_ * N_ + (size_t)(d0 + ty + r) * N_ + i0 + tx;
        g_Bt[o] = tile[tx][ty + r];
    }
}

// ---------------------------------------------------------------------------
// gemm1 on mma.sync fp16 hi/lo split (3 terms, ~2^-22 accuracy).
// C[j][d] = sum_k cost[k][j0+j] * Bt[d][k].  CTA tile 64j x 128d, K-chunk 16.
// Grid 32 x 8 = 256 CTAs -> 2 CTAs/SM for latency hiding.
// A smem: k-major [k][j] (direct coalesced store), ldmatrix.x4.trans.
// B smem: [d][k], ldmatrix.x4.  Fused degree count on cost loads.
// ---------------------------------------------------------------------------
__global__ __launch_bounds__(256, 2) void gemm1_mma_kernel(const float* __restrict__ cost)
{
    __shared__ __align__(16) __half sA[2][2][16 * APITCH];   // [stage][hi/lo]
    __shared__ __align__(16) __half sB[2][2][128 * BPITCH];

    const int tid = threadIdx.x, lane = tid & 31, w = tid >> 5;
    const int b = blockIdx.y, j0 = blockIdx.x * 64;
    const float* cB = cost + (size_t)b * N_ * N_;
    const float* bT = g_Bt + (size_t)b * D_ * N_;

    // load-role: A: thread t -> k=t>>4 (warp w covers rows 2w, 2w+1), j=(t&15)*4
    const int kA  = tid >> 4;
    const int jq  = tid & 15;
    // B: rows dB0, dB0+64, k-quad kqB
    const int dB0 = tid >> 2;
    const int kqB = tid & 3;

    // mma-role: warp tile 32m x 32n
    const int wm = w & 1, wn = w >> 1;
    const int m0w = wm * 32, n0w = wn * 32;
    const int rsel = (lane & 7) + ((lane & 16) ? 8 : 0);
    const int csel = (lane & 8) ? 8 : 0;

    float acc[2][4][4];
    #pragma unroll
    for (int mi = 0; mi < 2; mi++)
        #pragma unroll
        for (int ni = 0; ni < 4; ni++)
            #pragma unroll
            for (int q = 0; q < 4; q++) acc[mi][ni][q] = 0.f;

    float4 ca, eb0, eb1;

    // ---- prologue: load + store chunk 0 ----
    {
        ca  = *(const float4*)(cB + (size_t)kA * N_ + j0 + jq * 4);
        eb0 = *(const float4*)(bT + (size_t)dB0 * N_ + kqB * 4);
        eb1 = *(const float4*)(bT + (size_t)(dB0 + 64) * N_ + kqB * 4);

        unsigned mz = 0;
        mz  = __ballot_sync(~0u, ca.x != 0.f);
        int nz = __popc(mz & 0xffffu), nzh = __popc(mz >> 16);
        mz  = __ballot_sync(~0u, ca.y != 0.f); nz += __popc(mz & 0xffffu); nzh += __popc(mz >> 16);
        mz  = __ballot_sync(~0u, ca.z != 0.f); nz += __popc(mz & 0xffffu); nzh += __popc(mz >> 16);
        mz  = __ballot_sync(~0u, ca.w != 0.f); nz += __popc(mz & 0xffffu); nzh += __popc(mz >> 16);
        if (lane == 0)  atomicAdd(&g_deg[b * N_ + 2 * w], nz);
        if (lane == 16) atomicAdd(&g_deg[b * N_ + 2 * w + 1], nzh);

        uint32_t h0, h1, l0, l1;
        split_f4(ca, h0, h1, l0, l1);
        *(uint2*)&sA[0][0][kA * APITCH + jq * 4] = make_uint2(h0, h1);
        *(uint2*)&sA[0][1][kA * APITCH + jq * 4] = make_uint2(l0, l1);
        split_f4(eb0, h0, h1, l0, l1);
        *(uint2*)&sB[0][0][dB0 * BPITCH + kqB * 4] = make_uint2(h0, h1);
        *(uint2*)&sB[0][1][dB0 * BPITCH + kqB * 4] = make_uint2(l0, l1);
        split_f4(eb1, h0, h1, l0, l1);
        *(uint2*)&sB[0][0][(dB0 + 64) * BPITCH + kqB * 4] = make_uint2(h0, h1);
        *(uint2*)&sB[0][1][(dB0 + 64) * BPITCH + kqB * 4] = make_uint2(l0, l1);
    }
    __syncthreads();

    // ---- main loop ----
    for (int c = 0; c < NC; c++) {
        const int s = c & 1;
        const bool more = (c + 1 < NC);
        if (more) {
            const int i0 = (c + 1) * 16;
            ca  = *(const float4*)(cB + (size_t)(i0 + kA) * N_ + j0 + jq * 4);
            eb0 = *(const float4*)(bT + (size_t)dB0 * N_ + i0 + kqB * 4);
            eb1 = *(const float4*)(bT + (size_t)(dB0 + 64) * N_ + i0 + kqB * 4);
        }

        // consume stage s
        uint32_t ah[2][4], al[2][4], bh[2][4], bl[2][4];
        #pragma unroll
        for (int mi = 0; mi < 2; mi++) {
            ldsm4t(ah[mi], sm_addr(&sA[s][0][rsel * APITCH + m0w + mi * 16 + csel]));
            ldsm4t(al[mi], sm_addr(&sA[s][1][rsel * APITCH + m0w + mi * 16 + csel]));
        }
        #pragma unroll
        for (int nq = 0; nq < 2; nq++) {
            ldsm4(bh[nq], sm_addr(&sB[s][0][(n0w + nq * 16 + rsel) * BPITCH + csel]));
            ldsm4(bl[nq], sm_addr(&sB[s][1][(n0w + nq * 16 + rsel) * BPITCH + csel]));
        }
        #pragma unroll
        for (int mi = 0; mi < 2; mi++)
            #pragma unroll
            for (int ni = 0; ni < 4; ni++) {
                const uint32_t* BH = &bh[ni >> 1][(ni & 1) * 2];
                const uint32_t* BL = &bl[ni >> 1][(ni & 1) * 2];
                hmma(acc[mi][ni], ah[mi], BH);
                hmma(acc[mi][ni], ah[mi], BL);
                hmma(acc[mi][ni], al[mi], BH);
            }

        if (more) {
            const int i0 = (c + 1) * 16;
            unsigned mz;
            mz  = __ballot_sync(~0u, ca.x != 0.f);
            int nz = __popc(mz & 0xffffu), nzh = __popc(mz >> 16);
            mz  = __ballot_sync(~0u, ca.y != 0.f); nz += __popc(mz & 0xffffu); nzh += __popc(mz >> 16);
            mz  = __ballot_sync(~0u, ca.z != 0.f); nz += __popc(mz & 0xffffu); nzh += __popc(mz >> 16);
            mz  = __ballot_sync(~0u, ca.w != 0.f); nz += __popc(mz & 0xffffu); nzh += __popc(mz >> 16);
            if (lane == 0)  atomicAdd(&g_deg[b * N_ + i0 + 2 * w], nz);
            if (lane == 16) atomicAdd(&g_deg[b * N_ + i0 + 2 * w + 1], nzh);

            const int ns = s ^ 1;
            uint32_t h0, h1, l0, l1;
            split_f4(ca, h0, h1, l0, l1);
            *(uint2*)&sA[ns][0][kA * APITCH + jq * 4] = make_uint2(h0, h1);
            *(uint2*)&sA[ns][1][kA * APITCH + jq * 4] = make_uint2(l0, l1);
            split_f4(eb0, h0, h1, l0, l1);
            *(uint2*)&sB[ns][0][dB0 * BPITCH + kqB * 4] = make_uint2(h0, h1);
            *(uint2*)&sB[ns][1][dB0 * BPITCH + kqB * 4] = make_uint2(l0, l1);
            split_f4(eb1, h0, h1, l0, l1);
            *(uint2*)&sB[ns][0][(dB0 + 64) * BPITCH + kqB * 4] = make_uint2(h0, h1);
            *(uint2*)&sB[ns][1][(dB0 + 64) * BPITCH + kqB * 4] = make_uint2(l0, l1);
        }
        __syncthreads();
    }

    // ---- epilogue: fragments -> g_S[b][j][d] ----
    float* Sr = g_S + ((size_t)(b * N_ + j0)) * D_;
    #pragma unroll
    for (int mi = 0; mi < 2; mi++) {
        int r = m0w + mi * 16 + (lane >> 2);
        #pragma unroll
        for (int ni = 0; ni < 4; ni++) {
            int cix = n0w + ni * 8 + 2 * (lane & 3);
            *(float2*)(Sr + (size_t)r * D_ + cix)       = make_float2(acc[mi][ni][0], acc[mi][ni][1]);
            *(float2*)(Sr + (size_t)(r + 8) * D_ + cix) = make_float2(acc[mi][ni][2], acc[mi][ni][3]);
        }
    }
}

// ---------------------------------------------------------------------------
// gemm2 (SIMT f32x2): out[n,d] = relu( X[n,:] @ Wt + bias )
//   X[n,f] = (f < 128) ? emb[n,f] : S[n,f-128] / degree[n]
// CTA tile 64n x 128d -> grid 256 -> 2+ CTAs/SM.
// ---------------------------------------------------------------------------
#define KC 16
__global__ __launch_bounds__(256) void gemm2_kernel(
    const float* __restrict__ emb, const float* __restrict__ bias,
    float* __restrict__ out)
{
    __shared__ float Xs[KC][64];    // [f][n]
    __shared__ float Ws[KC][128];   // [f][d]

    const int n0 = blockIdx.x * 64;
    const int t = threadIdx.x, lane = t & 31, w = t >> 5;
    const int tx = t & 15, ty = t >> 4;

    const int nl = t & 63;          // local n row this thread loads
    const int fg = t >> 6;          // f-quad group (0..3)
    const int nglob = n0 + nl;
    const float invdeg = 1.0f / (float)g_deg[nglob];

    ull acc[4][4];
    #pragma unroll
    for (int j = 0; j < 4; j++)
        #pragma unroll
        for (int p = 0; p < 4; p++) acc[j][p] = pack2(0.f, 0.f);

    for (int k0 = 0; k0 < 2 * D_; k0 += KC) {
        const float* src = (k0 < D_)
            ? (emb + (size_t)nglob * D_ + k0)
            : (g_S + (size_t)nglob * D_ + (k0 - D_));
        const float scale = (k0 < D_) ? 1.0f : invdeg;
        float4 x0 = *(const float4*)(src + fg * 4);
        float4 w0 = *(const float4*)(g_Wt + (size_t)(k0 + w) * 128 + lane * 4);
        float4 w1 = *(const float4*)(g_Wt + (size_t)(k0 + w + 8) * 128 + lane * 4);

        __syncthreads();
        int f0 = fg * 4;
        Xs[f0 + 0][nl] = x0.x * scale;  Xs[f0 + 1][nl] = x0.y * scale;
        Xs[f0 + 2][nl] = x0.z * scale;  Xs[f0 + 3][nl] = x0.w * scale;
        *(float4*)&Ws[w][lane * 4] = w0;
        *(float4*)&Ws[w + 8][lane * 4] = w1;
        __syncthreads();

        #pragma unroll
        for (int kk = 0; kk < KC; kk++) {
            float a0 = Xs[kk][ty * 4 + 0];
            float a1 = Xs[kk][ty * 4 + 1];
            float a2 = Xs[kk][ty * 4 + 2];
            float a3 = Xs[kk][ty * 4 + 3];
            float4 bv0 = *(const float4*)&Ws[kk][tx * 4];
            float4 bv1 = *(const float4*)&Ws[kk][64 + tx * 4];
            ull bp[4] = { pack2(bv0.x, bv0.y), pack2(bv0.z, bv0.w),
                          pack2(bv1.x, bv1.y), pack2(bv1.z, bv1.w) };
            float aj[4] = { a0, a1, a2, a3 };
            #pragma unroll
            for (int j = 0; j < 4; j++) {
                ull ad = pack2(aj[j], aj[j]);
                #pragma unroll
                for (int p = 0; p < 4; p++) fma2(acc[j][p], ad, bp[p]);
            }
        }
    }

    float4 bb0 = *(const float4*)(bias + tx * 4);
    float4 bb1 = *(const float4*)(bias + 64 + tx * 4);

    #pragma unroll
    for (int j = 0; j < 4; j++) {
        int nn = ty * 4 + j;
        float* Or = out + (size_t)(n0 + nn) * D_;
        float2 p0 = unpack2(acc[j][0]), p1 = unpack2(acc[j][1]);
        float2 p2 = unpack2(acc[j][2]), p3 = unpack2(acc[j][3]);
        float4 lo = make_float4(fmaxf(p0.x + bb0.x, 0.f), fmaxf(p0.y + bb0.y, 0.f),
                                fmaxf(p1.x + bb0.z, 0.f), fmaxf(p1.y + bb0.w, 0.f));
        float4 hi = make_float4(fmaxf(p2.x + bb1.x, 0.f), fmaxf(p2.y + bb1.y, 0.f),
                                fmaxf(p3.x + bb1.z, 0.f), fmaxf(p3.y + bb1.w, 0.f));
        *(float4*)(Or + tx * 4) = lo;
        *(float4*)(Or + 64 + tx * 4) = hi;
    }
}

// ---------------------------------------------------------------------------
extern "C" void kernel_launch(void* const* d_in, const int* in_sizes, int n_in,
                              void* d_out, int out_size)
{
    const float *emb = nullptr, *cost = nullptr, *W = nullptr, *bias = nullptr;
    for (int i = 0; i < n_in; i++) {
        int s = in_sizes[i];
        if      (s == B_ * N_ * N_) cost = (const float*)d_in[i];
        else if (s == B_ * N_ * D_) emb  = (const float*)d_in[i];
        else if (s == 2 * D_ * D_)  W    = (const float*)d_in[i];
        else if (s == D_)           bias = (const float*)d_in[i];
    }

    prep_kernel<<<128, 256>>>(W);
    prep2_kernel<<<dim3(N_ / 32, D_ / 32, B_), dim3(32, 8)>>>(emb);
    gemm1_mma_kernel<<<dim3(32, 8), 256>>>(cost);
    gemm2_kernel<<<256, 256>>>(emb, bias, (float*)d_out);
}

// round 6
// speedup vs baseline: 1.6426x; 1.6426x over previous
#include <cuda_runtime.h>
#include <cuda_fp16.h>
#include <cstdint>

#define B_ 8
#define N_ 2048
#define D_ 128
#define NCK 64                // k-chunks per CTA (split-K=2: 64 x 16 = 1024)
#define SHALF (B_ * N_ * D_)
#define APITCH 136            // halfs per A k-row (128 j + pad) -> 272B
#define BPITCH 24             // halfs per B d-row (16 k + pad) -> 48B

// ---------------------------------------------------------------------------
// Device scratch (no runtime allocation allowed)
// ---------------------------------------------------------------------------
__device__ float g_S[2 * SHALF];        // two split-K partial sums (64 MB)
__device__ int   g_deg[B_ * N_];        // nnz per cost row
__device__ float g_Wt[2 * D_ * D_];     // W transposed: Wt[f][d]
__device__ float g_Bt[B_ * D_ * N_];    // emb transposed: Bt[b][d][i] (8 MB)

typedef unsigned long long ull;

// ---------------------------------------------------------------------------
// helpers
// ---------------------------------------------------------------------------
__device__ __forceinline__ void hmma(float* c, const uint32_t* a, const uint32_t* b) {
    asm volatile(
        "mma.sync.aligned.m16n8k16.row.col.f32.f16.f16.f32 "
        "{%0,%1,%2,%3}, {%4,%5,%6,%7}, {%8,%9}, {%0,%1,%2,%3};"
        : "+f"(c[0]), "+f"(c[1]), "+f"(c[2]), "+f"(c[3])
        : "r"(a[0]), "r"(a[1]), "r"(a[2]), "r"(a[3]), "r"(b[0]), "r"(b[1]));
}
__device__ __forceinline__ void ldsm4(uint32_t* r, uint32_t addr) {
    asm volatile("ldmatrix.sync.aligned.m8n8.x4.shared.b16 {%0,%1,%2,%3}, [%4];"
                 : "=r"(r[0]), "=r"(r[1]), "=r"(r[2]), "=r"(r[3]) : "r"(addr));
}
__device__ __forceinline__ void ldsm4t(uint32_t* r, uint32_t addr) {
    asm volatile("ldmatrix.sync.aligned.m8n8.x4.trans.shared.b16 {%0,%1,%2,%3}, [%4];"
                 : "=r"(r[0]), "=r"(r[1]), "=r"(r[2]), "=r"(r[3]) : "r"(addr));
}
__device__ __forceinline__ uint32_t sm_addr(const void* p) {
    return (uint32_t)__cvta_generic_to_shared(p);
}
// exact fp32 -> fp16 hi/lo split of a float4, packed as half2 words
__device__ __forceinline__ void split_f4(float4 v, uint32_t& h0, uint32_t& h1,
                                         uint32_t& l0, uint32_t& l1) {
    __half2 a = __floats2half2_rn(v.x, v.y);
    __half2 b = __floats2half2_rn(v.z, v.w);
    float2 af = __half22float2(a), bf = __half22float2(b);
    __half2 c = __floats2half2_rn(v.x - af.x, v.y - af.y);
    __half2 d = __floats2half2_rn(v.z - bf.x, v.w - bf.y);
    h0 = *(uint32_t*)&a; h1 = *(uint32_t*)&b;
    l0 = *(uint32_t*)&c; l1 = *(uint32_t*)&d;
}
// f32x2 helpers for the SIMT gemm2
__device__ __forceinline__ ull pack2(float lo, float hi) {
    ull r; asm("mov.b64 %0, {%1,%2};" : "=l"(r) : "f"(lo), "f"(hi)); return r;
}
__device__ __forceinline__ void fma2(ull& d, ull a, ull b) {
    asm("fma.rn.f32x2 %0, %1, %2, %3;" : "=l"(d) : "l"(a), "l"(b), "l"(d));
}
__device__ __forceinline__ float2 unpack2(ull v) {
    float2 r; asm("mov.b64 {%0,%1}, %2;" : "=f"(r.x), "=f"(r.y) : "l"(v)); return r;
}

// ---------------------------------------------------------------------------
// prep: zero degree counters, transpose W into Wt[f][d]
// ---------------------------------------------------------------------------
__global__ void prep_kernel(const float* __restrict__ W) {
    int i = blockIdx.x * 256 + threadIdx.x;
    if (i < B_ * N_) g_deg[i] = 0;
    if (i < 2 * D_ * D_) {
        int f = i >> 7, d = i & 127;
        g_Wt[i] = W[d * 2 * D_ + f];
    }
}

// ---------------------------------------------------------------------------
// prep2: transpose emb[b][i][d] -> g_Bt[b][d][i]
// ---------------------------------------------------------------------------
__global__ void prep2_kernel(const float* __restrict__ emb) {
    __shared__ float tile[32][33];
    int b = blockIdx.z;
    int i0 = blockIdx.x * 32;
    int d0 = blockIdx.y * 32;
    int tx = threadIdx.x, ty = threadIdx.y;   // (32, 8)
    const float* eB = emb + (size_t)b * N_ * D_;
    #pragma unroll
    for (int r = 0; r < 32; r += 8)
        tile[ty + r][tx] = eB[(size_t)(i0 + ty + r) * D_ + d0 + tx];
    __syncthreads();
    #pragma unroll
    for (int r = 0; r < 32; r += 8) {
        size_t o = (size_t)b * D_ * N_ + (size_t)(d0 + ty + r) * N_ + i0 + tx;
        g_Bt[o] = tile[tx][ty + r];
    }
}

// ---------------------------------------------------------------------------
// gemm1 on mma.sync fp16 hi/lo split (3 terms, ~2^-22 accuracy), split-K=2.
// C[j][d] += cost[k][j0+j] * Bt[d][k] over this CTA's K half (1024).
// CTA tile 128j x 128d, chunk 16, grid (16, 8, 2) = 256 CTAs -> 2 CTAs/SM.
// Chunk body order: global load -> split/store into next stage (drained one
// iteration ago, so barrier-safe) -> ldsm+mma on current stage -> barrier.
// This keeps prefetch registers short-lived so the kernel fits 128 regs.
// ---------------------------------------------------------------------------
__global__ __launch_bounds__(256, 2) void gemm1_mma_kernel(const float* __restrict__ cost)
{
    __shared__ __align__(16) __half sA[2][2][16 * APITCH];   // [stage][hi/lo]
    __shared__ __align__(16) __half sB[2][2][128 * BPITCH];

    const int tid = threadIdx.x, lane = tid & 31, w = tid >> 5;
    const int b = blockIdx.y, j0 = blockIdx.x * 128;
    const int kz = blockIdx.z, kbase = kz * (N_ / 2);
    const float* cB = cost + (size_t)b * N_ * N_;
    const float* bT = g_Bt + (size_t)b * D_ * N_;

    // load-role indices
    const int kkA = w;                 // this warp loads cost rows kkA, kkA+8
    const int jq  = lane;
    const int dB0 = tid >> 2;          // B rows dB0 and dB0+64
    const int kqB = tid & 3;

    // mma-role indices: warp tile 32m x 64n
    const int wm = w & 3, wn = w >> 2;
    const int m0w = wm * 32, n0w = wn * 64;
    const int rsel = (lane & 7) + ((lane & 16) ? 8 : 0);
    const int csel = (lane & 8) ? 8 : 0;

    float acc[2][8][4];
    #pragma unroll
    for (int mi = 0; mi < 2; mi++)
        #pragma unroll
        for (int ni = 0; ni < 8; ni++)
            #pragma unroll
            for (int q = 0; q < 4; q++) acc[mi][ni][q] = 0.f;

    // ---- prologue: load + degree + store chunk 0 into stage 0 ----
    {
        const int i0 = kbase;
        float4 ca0 = *(const float4*)(cB + (size_t)(i0 + kkA) * N_ + j0 + jq * 4);
        float4 ca1 = *(const float4*)(cB + (size_t)(i0 + kkA + 8) * N_ + j0 + jq * 4);
        float4 eb0 = *(const float4*)(bT + (size_t)dB0 * N_ + i0 + kqB * 4);
        float4 eb1 = *(const float4*)(bT + (size_t)(dB0 + 64) * N_ + i0 + kqB * 4);
        int nz0 = __popc(__ballot_sync(~0u, ca0.x != 0.f)) + __popc(__ballot_sync(~0u, ca0.y != 0.f))
                + __popc(__ballot_sync(~0u, ca0.z != 0.f)) + __popc(__ballot_sync(~0u, ca0.w != 0.f));
        int nz1 = __popc(__ballot_sync(~0u, ca1.x != 0.f)) + __popc(__ballot_sync(~0u, ca1.y != 0.f))
                + __popc(__ballot_sync(~0u, ca1.z != 0.f)) + __popc(__ballot_sync(~0u, ca1.w != 0.f));
        if (lane == 0) atomicAdd(&g_deg[b * N_ + i0 + kkA], nz0);
        if (lane == 1) atomicAdd(&g_deg[b * N_ + i0 + kkA + 8], nz1);

        uint32_t h0, h1, l0, l1;
        split_f4(ca0, h0, h1, l0, l1);
        *(uint2*)&sA[0][0][kkA * APITCH + jq * 4] = make_uint2(h0, h1);
        *(uint2*)&sA[0][1][kkA * APITCH + jq * 4] = make_uint2(l0, l1);
        split_f4(ca1, h0, h1, l0, l1);
        *(uint2*)&sA[0][0][(kkA + 8) * APITCH + jq * 4] = make_uint2(h0, h1);
        *(uint2*)&sA[0][1][(kkA + 8) * APITCH + jq * 4] = make_uint2(l0, l1);
        split_f4(eb0, h0, h1, l0, l1);
        *(uint2*)&sB[0][0][dB0 * BPITCH + kqB * 4] = make_uint2(h0, h1);
        *(uint2*)&sB[0][1][dB0 * BPITCH + kqB * 4] = make_uint2(l0, l1);
        split_f4(eb1, h0, h1, l0, l1);
        *(uint2*)&sB[0][0][(dB0 + 64) * BPITCH + kqB * 4] = make_uint2(h0, h1);
        *(uint2*)&sB[0][1][(dB0 + 64) * BPITCH + kqB * 4] = make_uint2(l0, l1);
    }
    __syncthreads();

    // ---- main loop ----
    for (int c = 0; c < NCK; c++) {
        const int s = c & 1;
        if (c + 1 < NCK) {
            // load + degree + store chunk c+1 into stage s^1 (drained at end of c-1)
            const int i0 = kbase + (c + 1) * 16;
            const int ns = s ^ 1;
            float4 ca0 = *(const float4*)(cB + (size_t)(i0 + kkA) * N_ + j0 + jq * 4);
            float4 ca1 = *(const float4*)(cB + (size_t)(i0 + kkA + 8) * N_ + j0 + jq * 4);
            float4 eb0 = *(const float4*)(bT + (size_t)dB0 * N_ + i0 + kqB * 4);
            float4 eb1 = *(const float4*)(bT + (size_t)(dB0 + 64) * N_ + i0 + kqB * 4);
            int nz0 = __popc(__ballot_sync(~0u, ca0.x != 0.f)) + __popc(__ballot_sync(~0u, ca0.y != 0.f))
                    + __popc(__ballot_sync(~0u, ca0.z != 0.f)) + __popc(__ballot_sync(~0u, ca0.w != 0.f));
            int nz1 = __popc(__ballot_sync(~0u, ca1.x != 0.f)) + __popc(__ballot_sync(~0u, ca1.y != 0.f))
                    + __popc(__ballot_sync(~0u, ca1.z != 0.f)) + __popc(__ballot_sync(~0u, ca1.w != 0.f));
            if (lane == 0) atomicAdd(&g_deg[b * N_ + i0 + kkA], nz0);
            if (lane == 1) atomicAdd(&g_deg[b * N_ + i0 + kkA + 8], nz1);

            uint32_t h0, h1, l0, l1;
            split_f4(ca0, h0, h1, l0, l1);
            *(uint2*)&sA[ns][0][kkA * APITCH + jq * 4] = make_uint2(h0, h1);
            *(uint2*)&sA[ns][1][kkA * APITCH + jq * 4] = make_uint2(l0, l1);
            split_f4(ca1, h0, h1, l0, l1);
            *(uint2*)&sA[ns][0][(kkA + 8) * APITCH + jq * 4] = make_uint2(h0, h1);
            *(uint2*)&sA[ns][1][(kkA + 8) * APITCH + jq * 4] = make_uint2(l0, l1);
            split_f4(eb0, h0, h1, l0, l1);
            *(uint2*)&sB[ns][0][dB0 * BPITCH + kqB * 4] = make_uint2(h0, h1);
            *(uint2*)&sB[ns][1][dB0 * BPITCH + kqB * 4] = make_uint2(l0, l1);
            split_f4(eb1, h0, h1, l0, l1);
            *(uint2*)&sB[ns][0][(dB0 + 64) * BPITCH + kqB * 4] = make_uint2(h0, h1);
            *(uint2*)&sB[ns][1][(dB0 + 64) * BPITCH + kqB * 4] = make_uint2(l0, l1);
        }

        // consume stage s
        uint32_t ah[2][4], al[2][4], bh[4][4], bl[4][4];
        #pragma unroll
        for (int mi = 0; mi < 2; mi++) {
            ldsm4t(ah[mi], sm_addr(&sA[s][0][rsel * APITCH + m0w + mi * 16 + csel]));
            ldsm4t(al[mi], sm_addr(&sA[s][1][rsel * APITCH + m0w + mi * 16 + csel]));
        }
        #pragma unroll
        for (int nq = 0; nq < 4; nq++) {
            ldsm4(bh[nq], sm_addr(&sB[s][0][(n0w + nq * 16 + rsel) * BPITCH + csel]));
            ldsm4(bl[nq], sm_addr(&sB[s][1][(n0w + nq * 16 + rsel) * BPITCH + csel]));
        }
        #pragma unroll
        for (int mi = 0; mi < 2; mi++)
            #pragma unroll
            for (int ni = 0; ni < 8; ni++) {
                const uint32_t* BH = &bh[ni >> 1][(ni & 1) * 2];
                const uint32_t* BL = &bl[ni >> 1][(ni & 1) * 2];
                hmma(acc[mi][ni], ah[mi], BH);
                hmma(acc[mi][ni], ah[mi], BL);
                hmma(acc[mi][ni], al[mi], BH);
            }
        __syncthreads();
    }

    // ---- epilogue: fragments -> g_S[kz][b][j][d] ----
    float* Sr = g_S + (size_t)kz * SHALF + ((size_t)(b * N_ + j0)) * D_;
    #pragma unroll
    for (int mi = 0; mi < 2; mi++) {
        int r = m0w + mi * 16 + (lane >> 2);
        #pragma unroll
        for (int ni = 0; ni < 8; ni++) {
            int cix = n0w + ni * 8 + 2 * (lane & 3);
            *(float2*)(Sr + (size_t)r * D_ + cix)       = make_float2(acc[mi][ni][0], acc[mi][ni][1]);
            *(float2*)(Sr + (size_t)(r + 8) * D_ + cix) = make_float2(acc[mi][ni][2], acc[mi][ni][3]);
        }
    }
}

// ---------------------------------------------------------------------------
// gemm2 (SIMT f32x2): out[n,d] = relu( X[n,:] @ Wt + bias )
//   X[n,f] = (f < 128) ? emb[n,f] : (S0[n,f-128]+S1[n,f-128]) / degree[n]
// CTA tile 64n x 128d with 128 threads (8x8 microtile preserved), grid 256.
// ---------------------------------------------------------------------------
#define KC 16
__global__ __launch_bounds__(128) void gemm2_kernel(
    const float* __restrict__ emb, const float* __restrict__ bias,
    float* __restrict__ out)
{
    __shared__ float Xs[KC][64];    // [f][n]
    __shared__ float Ws[KC][128];   // [f][d]

    const int n0 = blockIdx.x * 64;
    const int t = threadIdx.x, lane = t & 31, w = t >> 5;   // 4 warps
    const int tx = t & 15, ty = (t >> 4) & 7;

    const int nl = t & 63;          // local n row this thread loads
    const int fg = t >> 6;          // which 8-float half of the KC chunk
    const int nglob = n0 + nl;
    const float invdeg = 1.0f / (float)g_deg[nglob];

    ull acc[8][4];
    #pragma unroll
    for (int j = 0; j < 8; j++)
        #pragma unroll
        for (int p = 0; p < 4; p++) acc[j][p] = pack2(0.f, 0.f);

    for (int k0 = 0; k0 < 2 * D_; k0 += KC) {
        float4 x0, x1;
        if (k0 < D_) {
            const float* src = emb + (size_t)nglob * D_ + k0;
            x0 = *(const float4*)(src + fg * 8);
            x1 = *(const float4*)(src + fg * 8 + 4);
        } else {
            const float* s0p = g_S + (size_t)nglob * D_ + (k0 - D_);
            const float* s1p = s0p + SHALF;
            float4 a0 = *(const float4*)(s0p + fg * 8);
            float4 a1 = *(const float4*)(s0p + fg * 8 + 4);
            float4 b0 = *(const float4*)(s1p + fg * 8);
            float4 b1 = *(const float4*)(s1p + fg * 8 + 4);
            x0 = make_float4((a0.x + b0.x) * invdeg, (a0.y + b0.y) * invdeg,
                             (a0.z + b0.z) * invdeg, (a0.w + b0.w) * invdeg);
            x1 = make_float4((a1.x + b1.x) * invdeg, (a1.y + b1.y) * invdeg,
                             (a1.z + b1.z) * invdeg, (a1.w + b1.w) * invdeg);
        }
        float4 w0 = *(const float4*)(g_Wt + (size_t)(k0 + w) * 128 + lane * 4);
        float4 w1 = *(const float4*)(g_Wt + (size_t)(k0 + w + 4) * 128 + lane * 4);
        float4 w2 = *(const float4*)(g_Wt + (size_t)(k0 + w + 8) * 128 + lane * 4);
        float4 w3 = *(const float4*)(g_Wt + (size_t)(k0 + w + 12) * 128 + lane * 4);

        __syncthreads();
        int f0 = fg * 8;
        Xs[f0 + 0][nl] = x0.x;  Xs[f0 + 1][nl] = x0.y;
        Xs[f0 + 2][nl] = x0.z;  Xs[f0 + 3][nl] = x0.w;
        Xs[f0 + 4][nl] = x1.x;  Xs[f0 + 5][nl] = x1.y;
        Xs[f0 + 6][nl] = x1.z;  Xs[f0 + 7][nl] = x1.w;
        *(float4*)&Ws[w][lane * 4]      = w0;
        *(float4*)&Ws[w + 4][lane * 4]  = w1;
        *(float4*)&Ws[w + 8][lane * 4]  = w2;
        *(float4*)&Ws[w + 12][lane * 4] = w3;
        __syncthreads();

        #pragma unroll
        for (int kk = 0; kk < KC; kk++) {
            float4 av0 = *(const float4*)&Xs[kk][ty * 4];
            float4 av1 = *(const float4*)&Xs[kk][32 + ty * 4];
            float4 bv0 = *(const float4*)&Ws[kk][tx * 4];
            float4 bv1 = *(const float4*)&Ws[kk][64 + tx * 4];
            ull bp[4] = { pack2(bv0.x, bv0.y), pack2(bv0.z, bv0.w),
                          pack2(bv1.x, bv1.y), pack2(bv1.z, bv1.w) };
            float aj[8] = { av0.x, av0.y, av0.z, av0.w,
                            av1.x, av1.y, av1.z, av1.w };
            #pragma unroll
            for (int j = 0; j < 8; j++) {
                ull ad = pack2(aj[j], aj[j]);
                #pragma unroll
                for (int p = 0; p < 4; p++) fma2(acc[j][p], ad, bp[p]);
            }
        }
    }

    float4 bb0 = *(const float4*)(bias + tx * 4);
    float4 bb1 = *(const float4*)(bias + 64 + tx * 4);

    #pragma unroll
    for (int j = 0; j < 8; j++) {
        int nn = (j < 4) ? (ty * 4 + j) : (32 + ty * 4 + (j - 4));
        float* Or = out + (size_t)(n0 + nn) * D_;
        float2 p0 = unpack2(acc[j][0]), p1 = unpack2(acc[j][1]);
        float2 p2 = unpack2(acc[j][2]), p3 = unpack2(acc[j][3]);
        float4 lo = make_float4(fmaxf(p0.x + bb0.x, 0.f), fmaxf(p0.y + bb0.y, 0.f),
                                fmaxf(p1.x + bb0.z, 0.f), fmaxf(p1.y + bb0.w, 0.f));
        float4 hi = make_float4(fmaxf(p2.x + bb1.x, 0.f), fmaxf(p2.y + bb1.y, 0.f),
                                fmaxf(p3.x + bb1.z, 0.f), fmaxf(p3.y + bb1.w, 0.f));
        *(float4*)(Or + tx * 4) = lo;
        *(float4*)(Or + 64 + tx * 4) = hi;
    }
}

// ---------------------------------------------------------------------------
extern "C" void kernel_launch(void* const* d_in, const int* in_sizes, int n_in,
                              void* d_out, int out_size)
{
    const float *emb = nullptr, *cost = nullptr, *W = nullptr, *bias = nullptr;
    for (int i = 0; i < n_in; i++) {
        int s = in_sizes[i];
        if      (s == B_ * N_ * N_) cost = (const float*)d_in[i];
        else if (s == B_ * N_ * D_) emb  = (const float*)d_in[i];
        else if (s == 2 * D_ * D_)  W    = (const float*)d_in[i];
        else if (s == D_)           bias = (const float*)d_in[i];
    }

    prep_kernel<<<128, 256>>>(W);
    prep2_kernel<<<dim3(N_ / 32, D_ / 32, B_), dim3(32, 8)>>>(emb);
    gemm1_mma_kernel<<<dim3(16, 8, 2), 256>>>(cost);
    gemm2_kernel<<<256, 128>>>(emb, bias, (float*)d_out);
}

// round 7
// speedup vs baseline: 1.8010x; 1.0964x over previous
#include <cuda_runtime.h>
#include <cuda_fp16.h>
#include <cstdint>

#define B_ 8
#define N_ 2048
#define D_ 128
#define NCK 64                // gemm1 k-chunks per CTA (split-K=2: 64 x 16 = 1024)
#define SHALF (B_ * N_ * D_)
#define APITCH 136            // gemm1 A: halfs per k-row (128 j + pad) -> 272B
#define BPITCH 24             // gemm1 B / gemm2 W,X: halfs per row (16 k + pad) -> 48B

// ---------------------------------------------------------------------------
// Device scratch (no runtime allocation allowed)
// ---------------------------------------------------------------------------
__device__ float g_S[2 * SHALF];        // two split-K partial sums (64 MB)
__device__ int   g_deg[B_ * N_];        // nnz per cost row
__device__ float g_Bt[B_ * D_ * N_];    // emb transposed: Bt[b][d][i] (8 MB)

// ---------------------------------------------------------------------------
// helpers
// ---------------------------------------------------------------------------
__device__ __forceinline__ void hmma(float* c, const uint32_t* a, const uint32_t* b) {
    asm volatile(
        "mma.sync.aligned.m16n8k16.row.col.f32.f16.f16.f32 "
        "{%0,%1,%2,%3}, {%4,%5,%6,%7}, {%8,%9}, {%0,%1,%2,%3};"
        : "+f"(c[0]), "+f"(c[1]), "+f"(c[2]), "+f"(c[3])
        : "r"(a[0]), "r"(a[1]), "r"(a[2]), "r"(a[3]), "r"(b[0]), "r"(b[1]));
}
__device__ __forceinline__ void ldsm4(uint32_t* r, uint32_t addr) {
    asm volatile("ldmatrix.sync.aligned.m8n8.x4.shared.b16 {%0,%1,%2,%3}, [%4];"
                 : "=r"(r[0]), "=r"(r[1]), "=r"(r[2]), "=r"(r[3]) : "r"(addr));
}
__device__ __forceinline__ void ldsm4t(uint32_t* r, uint32_t addr) {
    asm volatile("ldmatrix.sync.aligned.m8n8.x4.trans.shared.b16 {%0,%1,%2,%3}, [%4];"
                 : "=r"(r[0]), "=r"(r[1]), "=r"(r[2]), "=r"(r[3]) : "r"(addr));
}
__device__ __forceinline__ uint32_t sm_addr(const void* p) {
    return (uint32_t)__cvta_generic_to_shared(p);
}
// exact fp32 -> fp16 hi/lo split of a float4, packed as half2 words
__device__ __forceinline__ void split_f4(float4 v, uint32_t& h0, uint32_t& h1,
                                         uint32_t& l0, uint32_t& l1) {
    __half2 a = __floats2half2_rn(v.x, v.y);
    __half2 b = __floats2half2_rn(v.z, v.w);
    float2 af = __half22float2(a), bf = __half22float2(b);
    __half2 c = __floats2half2_rn(v.x - af.x, v.y - af.y);
    __half2 d = __floats2half2_rn(v.z - bf.x, v.w - bf.y);
    h0 = *(uint32_t*)&a; h1 = *(uint32_t*)&b;
    l0 = *(uint32_t*)&c; l1 = *(uint32_t*)&d;
}

// ---------------------------------------------------------------------------
// prep2 (fused): transpose emb[b][i][d] -> g_Bt[b][d][i], zero g_deg
// ---------------------------------------------------------------------------
__global__ void prep2_kernel(const float* __restrict__ emb) {
    __shared__ float tile[32][33];
    int b = blockIdx.z;
    int i0 = blockIdx.x * 32;
    int d0 = blockIdx.y * 32;
    int tx = threadIdx.x, ty = threadIdx.y;   // (32, 8)
    int lbid = blockIdx.x + gridDim.x * (blockIdx.y + gridDim.y * blockIdx.z);
    int gid = lbid * 256 + ty * 32 + tx;
    if (gid < B_ * N_) g_deg[gid] = 0;

    const float* eB = emb + (size_t)b * N_ * D_;
    #pragma unroll
    for (int r = 0; r < 32; r += 8)
        tile[ty + r][tx] = eB[(size_t)(i0 + ty + r) * D_ + d0 + tx];
    __syncthreads();
    #pragma unroll
    for (int r = 0; r < 32; r += 8) {
        size_t o = (size_t)b * D_ * N_ + (size_t)(d0 + ty + r) * N_ + i0 + tx;
        g_Bt[o] = tile[tx][ty + r];
    }
}

// ---------------------------------------------------------------------------
// gemm1 on mma.sync fp16 hi/lo split (3 terms), split-K=2.
// C[j][d] += cost[k][j0+j] * Bt[d][k] over this CTA's K half (1024).
// CTA tile 128j x 128d, chunk 16, grid (16, 8, 2) = 256 CTAs -> 2 CTAs/SM.
// ---------------------------------------------------------------------------
__global__ __launch_bounds__(256, 2) void gemm1_mma_kernel(const float* __restrict__ cost)
{
    __shared__ __align__(16) __half sA[2][2][16 * APITCH];   // [stage][hi/lo]
    __shared__ __align__(16) __half sB[2][2][128 * BPITCH];

    const int tid = threadIdx.x, lane = tid & 31, w = tid >> 5;
    const int b = blockIdx.y, j0 = blockIdx.x * 128;
    const int kz = blockIdx.z, kbase = kz * (N_ / 2);
    const float* cB = cost + (size_t)b * N_ * N_;
    const float* bT = g_Bt + (size_t)b * D_ * N_;

    // load-role indices
    const int kkA = w;                 // this warp loads cost rows kkA, kkA+8
    const int jq  = lane;
    const int dB0 = tid >> 2;          // B rows dB0 and dB0+64
    const int kqB = tid & 3;

    // mma-role indices: warp tile 32m x 64n
    const int wm = w & 3, wn = w >> 2;
    const int m0w = wm * 32, n0w = wn * 64;
    const int rsel = (lane & 7) + ((lane & 16) ? 8 : 0);
    const int csel = (lane & 8) ? 8 : 0;

    float acc[2][8][4];
    #pragma unroll
    for (int mi = 0; mi < 2; mi++)
        #pragma unroll
        for (int ni = 0; ni < 8; ni++)
            #pragma unroll
            for (int q = 0; q < 4; q++) acc[mi][ni][q] = 0.f;

    // ---- prologue: load + degree + store chunk 0 into stage 0 ----
    {
        const int i0 = kbase;
        float4 ca0 = *(const float4*)(cB + (size_t)(i0 + kkA) * N_ + j0 + jq * 4);
        float4 ca1 = *(const float4*)(cB + (size_t)(i0 + kkA + 8) * N_ + j0 + jq * 4);
        float4 eb0 = *(const float4*)(bT + (size_t)dB0 * N_ + i0 + kqB * 4);
        float4 eb1 = *(const float4*)(bT + (size_t)(dB0 + 64) * N_ + i0 + kqB * 4);
        int c0 = (ca0.x != 0.f) + (ca0.y != 0.f) + (ca0.z != 0.f) + (ca0.w != 0.f);
        int c1 = (ca1.x != 0.f) + (ca1.y != 0.f) + (ca1.z != 0.f) + (ca1.w != 0.f);
        c0 = __reduce_add_sync(0xffffffffu, c0);
        c1 = __reduce_add_sync(0xffffffffu, c1);
        if (lane == 0) atomicAdd(&g_deg[b * N_ + i0 + kkA], c0);
        if (lane == 1) atomicAdd(&g_deg[b * N_ + i0 + kkA + 8], c1);

        uint32_t h0, h1, l0, l1;
        split_f4(ca0, h0, h1, l0, l1);
        *(uint2*)&sA[0][0][kkA * APITCH + jq * 4] = make_uint2(h0, h1);
        *(uint2*)&sA[0][1][kkA * APITCH + jq * 4] = make_uint2(l0, l1);
        split_f4(ca1, h0, h1, l0, l1);
        *(uint2*)&sA[0][0][(kkA + 8) * APITCH + jq * 4] = make_uint2(h0, h1);
        *(uint2*)&sA[0][1][(kkA + 8) * APITCH + jq * 4] = make_uint2(l0, l1);
        split_f4(eb0, h0, h1, l0, l1);
        *(uint2*)&sB[0][0][dB0 * BPITCH + kqB * 4] = make_uint2(h0, h1);
        *(uint2*)&sB[0][1][dB0 * BPITCH + kqB * 4] = make_uint2(l0, l1);
        split_f4(eb1, h0, h1, l0, l1);
        *(uint2*)&sB[0][0][(dB0 + 64) * BPITCH + kqB * 4] = make_uint2(h0, h1);
        *(uint2*)&sB[0][1][(dB0 + 64) * BPITCH + kqB * 4] = make_uint2(l0, l1);
    }
    __syncthreads();

    // ---- main loop ----
    for (int c = 0; c < NCK; c++) {
        const int s = c & 1;
        if (c + 1 < NCK) {
            const int i0 = kbase + (c + 1) * 16;
            const int ns = s ^ 1;
            float4 ca0 = *(const float4*)(cB + (size_t)(i0 + kkA) * N_ + j0 + jq * 4);
            float4 ca1 = *(const float4*)(cB + (size_t)(i0 + kkA + 8) * N_ + j0 + jq * 4);
            float4 eb0 = *(const float4*)(bT + (size_t)dB0 * N_ + i0 + kqB * 4);
            float4 eb1 = *(const float4*)(bT + (size_t)(dB0 + 64) * N_ + i0 + kqB * 4);
            int c0 = (ca0.x != 0.f) + (ca0.y != 0.f) + (ca0.z != 0.f) + (ca0.w != 0.f);
            int c1 = (ca1.x != 0.f) + (ca1.y != 0.f) + (ca1.z != 0.f) + (ca1.w != 0.f);
            c0 = __reduce_add_sync(0xffffffffu, c0);
            c1 = __reduce_add_sync(0xffffffffu, c1);
            if (lane == 0) atomicAdd(&g_deg[b * N_ + i0 + kkA], c0);
            if (lane == 1) atomicAdd(&g_deg[b * N_ + i0 + kkA + 8], c1);

            uint32_t h0, h1, l0, l1;
            split_f4(ca0, h0, h1, l0, l1);
            *(uint2*)&sA[ns][0][kkA * APITCH + jq * 4] = make_uint2(h0, h1);
            *(uint2*)&sA[ns][1][kkA * APITCH + jq * 4] = make_uint2(l0, l1);
            split_f4(ca1, h0, h1, l0, l1);
            *(uint2*)&sA[ns][0][(kkA + 8) * APITCH + jq * 4] = make_uint2(h0, h1);
            *(uint2*)&sA[ns][1][(kkA + 8) * APITCH + jq * 4] = make_uint2(l0, l1);
            split_f4(eb0, h0, h1, l0, l1);
            *(uint2*)&sB[ns][0][dB0 * BPITCH + kqB * 4] = make_uint2(h0, h1);
            *(uint2*)&sB[ns][1][dB0 * BPITCH + kqB * 4] = make_uint2(l0, l1);
            split_f4(eb1, h0, h1, l0, l1);
            *(uint2*)&sB[ns][0][(dB0 + 64) * BPITCH + kqB * 4] = make_uint2(h0, h1);
            *(uint2*)&sB[ns][1][(dB0 + 64) * BPITCH + kqB * 4] = make_uint2(l0, l1);
        }

        // consume stage s
        uint32_t ah[2][4], al[2][4], bh[4][4], bl[4][4];
        #pragma unroll
        for (int mi = 0; mi < 2; mi++) {
            ldsm4t(ah[mi], sm_addr(&sA[s][0][rsel * APITCH + m0w + mi * 16 + csel]));
            ldsm4t(al[mi], sm_addr(&sA[s][1][rsel * APITCH + m0w + mi * 16 + csel]));
        }
        #pragma unroll
        for (int nq = 0; nq < 4; nq++) {
            ldsm4(bh[nq], sm_addr(&sB[s][0][(n0w + nq * 16 + rsel) * BPITCH + csel]));
            ldsm4(bl[nq], sm_addr(&sB[s][1][(n0w + nq * 16 + rsel) * BPITCH + csel]));
        }
        #pragma unroll
        for (int mi = 0; mi < 2; mi++)
            #pragma unroll
            for (int ni = 0; ni < 8; ni++) {
                const uint32_t* BH = &bh[ni >> 1][(ni & 1) * 2];
                const uint32_t* BL = &bl[ni >> 1][(ni & 1) * 2];
                hmma(acc[mi][ni], ah[mi], BH);
                hmma(acc[mi][ni], ah[mi], BL);
                hmma(acc[mi][ni], al[mi], BH);
            }
        __syncthreads();
    }

    // ---- epilogue: fragments -> g_S[kz][b][j][d] ----
    float* Sr = g_S + (size_t)kz * SHALF + ((size_t)(b * N_ + j0)) * D_;
    #pragma unroll
    for (int mi = 0; mi < 2; mi++) {
        int r = m0w + mi * 16 + (lane >> 2);
        #pragma unroll
        for (int ni = 0; ni < 8; ni++) {
            int cix = n0w + ni * 8 + 2 * (lane & 3);
            *(float2*)(Sr + (size_t)r * D_ + cix)       = make_float2(acc[mi][ni][0], acc[mi][ni][1]);
            *(float2*)(Sr + (size_t)(r + 8) * D_ + cix) = make_float2(acc[mi][ni][2], acc[mi][ni][3]);
        }
    }
}

// ---------------------------------------------------------------------------
// gemm2 on mma.sync fp16 hi/lo split (3 terms):
//   out[n,d] = relu( sum_f X[n,f] * W[d,f] + bias[d] )
//   X[n,f] = (f < 128) ? emb[n,f] : (S0[n,f-128]+S1[n,f-128]) / degree[n]
// CTA tile 64n x 128d, K = 256 in 16 chunks, grid 256, 256 threads.
// Warp tile 16m x 64n (m = out-rows, n = d).  W used directly ([d][f],
// f-contiguous = col-major B fragments). X: non-trans ldsm on [n][f].
// ---------------------------------------------------------------------------
__global__ __launch_bounds__(256, 2) void gemm2_mma_kernel(
    const float* __restrict__ emb, const float* __restrict__ W,
    const float* __restrict__ bias, float* __restrict__ out)
{
    __shared__ __align__(16) __half sX[2][2][64 * BPITCH];    // [stage][hi/lo][n][f]
    __shared__ __align__(16) __half sW[2][2][128 * BPITCH];   // [stage][hi/lo][d][f]

    const int tid = threadIdx.x, lane = tid & 31, w = tid >> 5;
    const int gn0 = blockIdx.x * 64;

    // producer roles
    const int nX = tid >> 2, fqX = (tid & 3) * 4;   // X: row nX, f-quad fqX
    const int dW = tid & 127, qW = tid >> 7;        // W: row dW, 8-f half qW
    const float invdeg = 1.0f / (float)g_deg[gn0 + nX];

    // mma roles: warp tile 16m x 64n; 4 m-slots x 2 n-slots
    const int wm = w & 3, wn = w >> 2;
    const int m0w = wm * 16, n0w = wn * 64;
    const int rA = lane & 15, cA = (lane & 16) ? 8 : 0;          // A row-major map
    const int rsel = (lane & 7) + ((lane & 16) ? 8 : 0);         // B map (proven)
    const int csel = (lane & 8) ? 8 : 0;

    float acc[8][4];
    #pragma unroll
    for (int ni = 0; ni < 8; ni++)
        #pragma unroll
        for (int q = 0; q < 4; q++) acc[ni][q] = 0.f;

    // bias preload (per-thread columns)
    float2 bb[8];
    #pragma unroll
    for (int ni = 0; ni < 8; ni++) {
        int cix = n0w + ni * 8 + 2 * (lane & 3);
        bb[ni] = make_float2(bias[cix], bias[cix + 1]);
    }

    // producer: fill stage st with f-chunk k0
    auto fill = [&](int k0, int st) {
        float4 xv;
        if (k0 < D_) {
            xv = *(const float4*)(emb + (size_t)(gn0 + nX) * D_ + k0 + fqX);
        } else {
            const float* s0p = g_S + (size_t)(gn0 + nX) * D_ + (k0 - D_) + fqX;
            float4 a = *(const float4*)s0p;
            float4 bq = *(const float4*)(s0p + SHALF);
            xv = make_float4((a.x + bq.x) * invdeg, (a.y + bq.y) * invdeg,
                             (a.z + bq.z) * invdeg, (a.w + bq.w) * invdeg);
        }
        float4 wv0 = *(const float4*)(W + (size_t)dW * 256 + k0 + qW * 8);
        float4 wv1 = *(const float4*)(W + (size_t)dW * 256 + k0 + qW * 8 + 4);

        uint32_t h0, h1, l0, l1;
        split_f4(xv, h0, h1, l0, l1);
        *(uint2*)&sX[st][0][nX * BPITCH + fqX] = make_uint2(h0, h1);
        *(uint2*)&sX[st][1][nX * BPITCH + fqX] = make_uint2(l0, l1);
        split_f4(wv0, h0, h1, l0, l1);
        *(uint2*)&sW[st][0][dW * BPITCH + qW * 8] = make_uint2(h0, h1);
        *(uint2*)&sW[st][1][dW * BPITCH + qW * 8] = make_uint2(l0, l1);
        split_f4(wv1, h0, h1, l0, l1);
        *(uint2*)&sW[st][0][dW * BPITCH + qW * 8 + 4] = make_uint2(h0, h1);
        *(uint2*)&sW[st][1][dW * BPITCH + qW * 8 + 4] = make_uint2(l0, l1);
    };

    fill(0, 0);
    __syncthreads();

    for (int c = 0; c < 16; c++) {
        const int s = c & 1;
        if (c + 1 < 16) fill((c + 1) * 16, s ^ 1);

        uint32_t ah[4], al[4], bh[4][4], bl[4][4];
        ldsm4(ah, sm_addr(&sX[s][0][(m0w + rA) * BPITCH + cA]));
        ldsm4(al, sm_addr(&sX[s][1][(m0w + rA) * BPITCH + cA]));
        #pragma unroll
        for (int nq = 0; nq < 4; nq++) {
            ldsm4(bh[nq], sm_addr(&sW[s][0][(n0w + nq * 16 + rsel) * BPITCH + csel]));
            ldsm4(bl[nq], sm_addr(&sW[s][1][(n0w + nq * 16 + rsel) * BPITCH + csel]));
        }
        #pragma unroll
        for (int ni = 0; ni < 8; ni++) {
            const uint32_t* BH = &bh[ni >> 1][(ni & 1) * 2];
            const uint32_t* BL = &bl[ni >> 1][(ni & 1) * 2];
            hmma(acc[ni], ah, BH);
            hmma(acc[ni], ah, BL);
            hmma(acc[ni], al, BH);
        }
        __syncthreads();
    }

    // epilogue: bias + relu + store
    const int r = m0w + (lane >> 2);
    #pragma unroll
    for (int ni = 0; ni < 8; ni++) {
        int cix = n0w + ni * 8 + 2 * (lane & 3);
        float* O0 = out + (size_t)(gn0 + r) * D_ + cix;
        float* O1 = out + (size_t)(gn0 + r + 8) * D_ + cix;
        *(float2*)O0 = make_float2(fmaxf(acc[ni][0] + bb[ni].x, 0.f),
                                   fmaxf(acc[ni][1] + bb[ni].y, 0.f));
        *(float2*)O1 = make_float2(fmaxf(acc[ni][2] + bb[ni].x, 0.f),
                                   fmaxf(acc[ni][3] + bb[ni].y, 0.f));
    }
}

// ---------------------------------------------------------------------------
extern "C" void kernel_launch(void* const* d_in, const int* in_sizes, int n_in,
                              void* d_out, int out_size)
{
    const float *emb = nullptr, *cost = nullptr, *W = nullptr, *bias = nullptr;
    for (int i = 0; i < n_in; i++) {
        int s = in_sizes[i];
        if      (s == B_ * N_ * N_) cost = (const float*)d_in[i];
        else if (s == B_ * N_ * D_) emb  = (const float*)d_in[i];
        else if (s == 2 * D_ * D_)  W    = (const float*)d_in[i];
        else if (s == D_)           bias = (const float*)d_in[i];
    }

    prep2_kernel<<<dim3(N_ / 32, D_ / 32, B_), dim3(32, 8)>>>(emb);
    gemm1_mma_kernel<<<dim3(16, 8, 2), 256>>>(cost);
    gemm2_mma_kernel<<<256, 256>>>(emb, W, bias, (float*)d_out);
}

// round 9
// speedup vs baseline: 1.9582x; 1.0873x over previous
#include <cuda_runtime.h>
#include <cuda_fp16.h>
#include <cstdint>

#define B_ 8
#define N_ 2048
#define D_ 128
#define NCK 64                // gemm1 k-chunks per CTA (split-K=2: 64 x 16 = 1024)
#define SHALF (B_ * N_ * D_)
#define APITCH 136            // gemm1 A: halfs per k-row (128 j + pad) -> 272B
#define BPITCH 24             // gemm1 B / gemm2 W,X: halfs per row (16 k + pad) -> 48B

// ---------------------------------------------------------------------------
// Device scratch (no runtime allocation allowed)
// ---------------------------------------------------------------------------
__device__ float g_S[2 * SHALF];        // two split-K partial sums (64 MB)
__device__ int   g_deg[B_ * N_];        // nnz per cost row
__device__ float g_Bt[B_ * D_ * N_];    // emb transposed: Bt[b][d][i] (8 MB)

// ---------------------------------------------------------------------------
// helpers
// ---------------------------------------------------------------------------
__device__ __forceinline__ void hmma(float* c, const uint32_t* a, const uint32_t* b) {
    asm volatile(
        "mma.sync.aligned.m16n8k16.row.col.f32.f16.f16.f32 "
        "{%0,%1,%2,%3}, {%4,%5,%6,%7}, {%8,%9}, {%0,%1,%2,%3};"
        : "+f"(c[0]), "+f"(c[1]), "+f"(c[2]), "+f"(c[3])
        : "r"(a[0]), "r"(a[1]), "r"(a[2]), "r"(a[3]), "r"(b[0]), "r"(b[1]));
}
__device__ __forceinline__ void ldsm4(uint32_t* r, uint32_t addr) {
    asm volatile("ldmatrix.sync.aligned.m8n8.x4.shared.b16 {%0,%1,%2,%3}, [%4];"
                 : "=r"(r[0]), "=r"(r[1]), "=r"(r[2]), "=r"(r[3]) : "r"(addr));
}
__device__ __forceinline__ void ldsm4t(uint32_t* r, uint32_t addr) {
    asm volatile("ldmatrix.sync.aligned.m8n8.x4.trans.shared.b16 {%0,%1,%2,%3}, [%4];"
                 : "=r"(r[0]), "=r"(r[1]), "=r"(r[2]), "=r"(r[3]) : "r"(addr));
}
__device__ __forceinline__ uint32_t sm_addr(const void* p) {
    return (uint32_t)__cvta_generic_to_shared(p);
}
// exact fp32 -> fp16 hi/lo split of a float4, packed as half2 words
__device__ __forceinline__ void split_f4(float4 v, uint32_t& h0, uint32_t& h1,
                                         uint32_t& l0, uint32_t& l1) {
    __half2 a = __floats2half2_rn(v.x, v.y);
    __half2 b = __floats2half2_rn(v.z, v.w);
    float2 af = __half22float2(a), bf = __half22float2(b);
    __half2 c = __floats2half2_rn(v.x - af.x, v.y - af.y);
    __half2 d = __floats2half2_rn(v.z - bf.x, v.w - bf.y);
    h0 = *(uint32_t*)&a; h1 = *(uint32_t*)&b;
    l0 = *(uint32_t*)&c; l1 = *(uint32_t*)&d;
}
// fp32 float4 -> fp16 (single rounding), packed as 2 half2 words
__device__ __forceinline__ void cvt_f4(float4 v, uint32_t& h0, uint32_t& h1) {
    __half2 a = __floats2half2_rn(v.x, v.y);
    __half2 b = __floats2half2_rn(v.z, v.w);
    h0 = *(uint32_t*)&a; h1 = *(uint32_t*)&b;
}

// ---------------------------------------------------------------------------
// prep2 (fused): transpose emb[b][i][d] -> g_Bt[b][d][i], zero g_deg
// ---------------------------------------------------------------------------
__global__ void prep2_kernel(const float* __restrict__ emb) {
    __shared__ float tile[32][33];
    int b = blockIdx.z;
    int i0 = blockIdx.x * 32;
    int d0 = blockIdx.y * 32;
    int tx = threadIdx.x, ty = threadIdx.y;   // (32, 8)
    int lbid = blockIdx.x + gridDim.x * (blockIdx.y + gridDim.y * blockIdx.z);
    int gid = lbid * 256 + ty * 32 + tx;
    if (gid < B_ * N_) g_deg[gid] = 0;

    const float* eB = emb + (size_t)b * N_ * D_;
    #pragma unroll
    for (int r = 0; r < 32; r += 8)
        tile[ty + r][tx] = eB[(size_t)(i0 + ty + r) * D_ + d0 + tx];
    __syncthreads();
    #pragma unroll
    for (int r = 0; r < 32; r += 8) {
        size_t o = (size_t)b * D_ * N_ + (size_t)(d0 + ty + r) * N_ + i0 + tx;
        g_Bt[o] = tile[tx][ty + r];
    }
}

// ---------------------------------------------------------------------------
// gemm1 on mma.sync, 2-term scheme: S ~= (a_hi + a_lo) * fp16(b).
// a = cost (exact 2-term fp16 split), b = emb (single fp16 rounding; the
// resulting ~1e-4 relative error on S is diluted ~10x by degree
// normalization + emb-dominated output of gemm2).
// C[j][d] += cost[k][j0+j] * Bt[d][k] over this CTA's K half (1024).
// CTA tile 128j x 128d, chunk 16, grid (16, 8, 2) = 256 CTAs -> 2 CTAs/SM.
// Per warp-chunk: 32 HMMA, 8 LDSM.
// ---------------------------------------------------------------------------
__global__ __launch_bounds__(256, 2) void gemm1_mma_kernel(const float* __restrict__ cost)
{
    __shared__ __align__(16) __half sA[2][2][16 * APITCH];   // [stage][hi/lo]
    __shared__ __align__(16) __half sB[2][128 * BPITCH];     // [stage], fp16 only

    const int tid = threadIdx.x, lane = tid & 31, w = tid >> 5;
    const int b = blockIdx.y, j0 = blockIdx.x * 128;
    const int kz = blockIdx.z, kbase = kz * (N_ / 2);
    const float* cB = cost + (size_t)b * N_ * N_;
    const float* bT = g_Bt + (size_t)b * D_ * N_;

    // load-role indices
    const int kkA = w;                 // this warp loads cost rows kkA, kkA+8
    const int jq  = lane;
    const int dB0 = tid >> 2;          // B rows dB0 and dB0+64
    const int kqB = tid & 3;

    // mma-role indices: warp tile 32m x 64n
    const int wm = w & 3, wn = w >> 2;
    const int m0w = wm * 32, n0w = wn * 64;
    const int rsel = (lane & 7) + ((lane & 16) ? 8 : 0);
    const int csel = (lane & 8) ? 8 : 0;

    float acc[2][8][4];
    #pragma unroll
    for (int mi = 0; mi < 2; mi++)
        #pragma unroll
        for (int ni = 0; ni < 8; ni++)
            #pragma unroll
            for (int q = 0; q < 4; q++) acc[mi][ni][q] = 0.f;

    // ---- prologue: load + degree + store chunk 0 into stage 0 ----
    {
        const int i0 = kbase;
        float4 ca0 = *(const float4*)(cB + (size_t)(i0 + kkA) * N_ + j0 + jq * 4);
        float4 ca1 = *(const float4*)(cB + (size_t)(i0 + kkA + 8) * N_ + j0 + jq * 4);
        float4 eb0 = *(const float4*)(bT + (size_t)dB0 * N_ + i0 + kqB * 4);
        float4 eb1 = *(const float4*)(bT + (size_t)(dB0 + 64) * N_ + i0 + kqB * 4);
        int c0 = (ca0.x != 0.f) + (ca0.y != 0.f) + (ca0.z != 0.f) + (ca0.w != 0.f);
        int c1 = (ca1.x != 0.f) + (ca1.y != 0.f) + (ca1.z != 0.f) + (ca1.w != 0.f);
        c0 = __reduce_add_sync(0xffffffffu, c0);
        c1 = __reduce_add_sync(0xffffffffu, c1);
        if (lane == 0) atomicAdd(&g_deg[b * N_ + i0 + kkA], c0);
        if (lane == 1) atomicAdd(&g_deg[b * N_ + i0 + kkA + 8], c1);

        uint32_t h0, h1, l0, l1;
        split_f4(ca0, h0, h1, l0, l1);
        *(uint2*)&sA[0][0][kkA * APITCH + jq * 4] = make_uint2(h0, h1);
        *(uint2*)&sA[0][1][kkA * APITCH + jq * 4] = make_uint2(l0, l1);
        split_f4(ca1, h0, h1, l0, l1);
        *(uint2*)&sA[0][0][(kkA + 8) * APITCH + jq * 4] = make_uint2(h0, h1);
        *(uint2*)&sA[0][1][(kkA + 8) * APITCH + jq * 4] = make_uint2(l0, l1);
        cvt_f4(eb0, h0, h1);
        *(uint2*)&sB[0][dB0 * BPITCH + kqB * 4] = make_uint2(h0, h1);
        cvt_f4(eb1, h0, h1);
        *(uint2*)&sB[0][(dB0 + 64) * BPITCH + kqB * 4] = make_uint2(h0, h1);
    }
    __syncthreads();

    // ---- main loop ----
    for (int c = 0; c < NCK; c++) {
        const int s = c & 1;
        if (c + 1 < NCK) {
            const int i0 = kbase + (c + 1) * 16;
            const int ns = s ^ 1;
            float4 ca0 = *(const float4*)(cB + (size_t)(i0 + kkA) * N_ + j0 + jq * 4);
            float4 ca1 = *(const float4*)(cB + (size_t)(i0 + kkA + 8) * N_ + j0 + jq * 4);
            float4 eb0 = *(const float4*)(bT + (size_t)dB0 * N_ + i0 + kqB * 4);
            float4 eb1 = *(const float4*)(bT + (size_t)(dB0 + 64) * N_ + i0 + kqB * 4);
            int c0 = (ca0.x != 0.f) + (ca0.y != 0.f) + (ca0.z != 0.f) + (ca0.w != 0.f);
            int c1 = (ca1.x != 0.f) + (ca1.y != 0.f) + (ca1.z != 0.f) + (ca1.w != 0.f);
            c0 = __reduce_add_sync(0xffffffffu, c0);
            c1 = __reduce_add_sync(0xffffffffu, c1);
            if (lane == 0) atomicAdd(&g_deg[b * N_ + i0 + kkA], c0);
            if (lane == 1) atomicAdd(&g_deg[b * N_ + i0 + kkA + 8], c1);

            uint32_t h0, h1, l0, l1;
            split_f4(ca0, h0, h1, l0, l1);
            *(uint2*)&sA[ns][0][kkA * APITCH + jq * 4] = make_uint2(h0, h1);
            *(uint2*)&sA[ns][1][kkA * APITCH + jq * 4] = make_uint2(l0, l1);
            split_f4(ca1, h0, h1, l0, l1);
            *(uint2*)&sA[ns][0][(kkA + 8) * APITCH + jq * 4] = make_uint2(h0, h1);
            *(uint2*)&sA[ns][1][(kkA + 8) * APITCH + jq * 4] = make_uint2(l0, l1);
            cvt_f4(eb0, h0, h1);
            *(uint2*)&sB[ns][dB0 * BPITCH + kqB * 4] = make_uint2(h0, h1);
            cvt_f4(eb1, h0, h1);
            *(uint2*)&sB[ns][(dB0 + 64) * BPITCH + kqB * 4] = make_uint2(h0, h1);
        }

        // consume stage s: 8 LDSM, 32 HMMA
        uint32_t ah[2][4], al[2][4], bh[4][4];
        #pragma unroll
        for (int mi = 0; mi < 2; mi++) {
            ldsm4t(ah[mi], sm_addr(&sA[s][0][rsel * APITCH + m0w + mi * 16 + csel]));
            ldsm4t(al[mi], sm_addr(&sA[s][1][rsel * APITCH + m0w + mi * 16 + csel]));
        }
        #pragma unroll
        for (int nq = 0; nq < 4; nq++)
            ldsm4(bh[nq], sm_addr(&sB[s][(n0w + nq * 16 + rsel) * BPITCH + csel]));
        #pragma unroll
        for (int mi = 0; mi < 2; mi++)
            #pragma unroll
            for (int ni = 0; ni < 8; ni++) {
                const uint32_t* BH = &bh[ni >> 1][(ni & 1) * 2];
                hmma(acc[mi][ni], ah[mi], BH);
                hmma(acc[mi][ni], al[mi], BH);
            }
        __syncthreads();
    }

    // ---- epilogue: fragments -> g_S[kz][b][j][d] ----
    float* Sr = g_S + (size_t)kz * SHALF + ((size_t)(b * N_ + j0)) * D_;
    #pragma unroll
    for (int mi = 0; mi < 2; mi++) {
        int r = m0w + mi * 16 + (lane >> 2);
        #pragma unroll
        for (int ni = 0; ni < 8; ni++) {
            int cix = n0w + ni * 8 + 2 * (lane & 3);
            *(float2*)(Sr + (size_t)r * D_ + cix)       = make_float2(acc[mi][ni][0], acc[mi][ni][1]);
            *(float2*)(Sr + (size_t)(r + 8) * D_ + cix) = make_float2(acc[mi][ni][2], acc[mi][ni][3]);
        }
    }
}

// ---------------------------------------------------------------------------
// gemm2 on mma.sync fp16 hi/lo split (3 terms):
//   out[n,d] = relu( sum_f X[n,f] * W[d,f] + bias[d] )
//   X[n,f] = (f < 128) ? emb[n,f] : (S0[n,f-128]+S1[n,f-128]) / degree[n]
// CTA tile 64n x 128d, K = 256 in 16 chunks, grid 256, 256 threads.
// ---------------------------------------------------------------------------
__global__ __launch_bounds__(256, 2) void gemm2_mma_kernel(
    const float* __restrict__ emb, const float* __restrict__ W,
    const float* __restrict__ bias, float* __restrict__ out)
{
    __shared__ __align__(16) __half sX[2][2][64 * BPITCH];    // [stage][hi/lo][n][f]
    __shared__ __align__(16) __half sW[2][2][128 * BPITCH];   // [stage][hi/lo][d][f]

    const int tid = threadIdx.x, lane = tid & 31, w = tid >> 5;
    const int gn0 = blockIdx.x * 64;

    // producer roles
    const int nX = tid >> 2, fqX = (tid & 3) * 4;   // X: row nX, f-quad fqX
    const int dW = tid & 127, qW = tid >> 7;        // W: row dW, 8-f half qW
    const float invdeg = 1.0f / (float)g_deg[gn0 + nX];

    // mma roles: warp tile 16m x 64n; 4 m-slots x 2 n-slots
    const int wm = w & 3, wn = w >> 2;
    const int m0w = wm * 16, n0w = wn * 64;
    const int rA = lane & 15, cA = (lane & 16) ? 8 : 0;          // A row-major map
    const int rsel = (lane & 7) + ((lane & 16) ? 8 : 0);         // B map (proven)
    const int csel = (lane & 8) ? 8 : 0;

    float acc[8][4];
    #pragma unroll
    for (int ni = 0; ni < 8; ni++)
        #pragma unroll
        for (int q = 0; q < 4; q++) acc[ni][q] = 0.f;

    // bias preload (per-thread columns)
    float2 bb[8];
    #pragma unroll
    for (int ni = 0; ni < 8; ni++) {
        int cix = n0w + ni * 8 + 2 * (lane & 3);
        bb[ni] = make_float2(bias[cix], bias[cix + 1]);
    }

    // producer: fill stage st with f-chunk k0
    auto fill = [&](int k0, int st) {
        float4 xv;
        if (k0 < D_) {
            xv = *(const float4*)(emb + (size_t)(gn0 + nX) * D_ + k0 + fqX);
        } else {
            const float* s0p = g_S + (size_t)(gn0 + nX) * D_ + (k0 - D_) + fqX;
            float4 a = *(const float4*)s0p;
            float4 bq = *(const float4*)(s0p + SHALF);
            xv = make_float4((a.x + bq.x) * invdeg, (a.y + bq.y) * invdeg,
                             (a.z + bq.z) * invdeg, (a.w + bq.w) * invdeg);
        }
        float4 wv0 = *(const float4*)(W + (size_t)dW * 256 + k0 + qW * 8);
        float4 wv1 = *(const float4*)(W + (size_t)dW * 256 + k0 + qW * 8 + 4);

        uint32_t h0, h1, l0, l1;
        split_f4(xv, h0, h1, l0, l1);
        *(uint2*)&sX[st][0][nX * BPITCH + fqX] = make_uint2(h0, h1);
        *(uint2*)&sX[st][1][nX * BPITCH + fqX] = make_uint2(l0, l1);
        split_f4(wv0, h0, h1, l0, l1);
        *(uint2*)&sW[st][0][dW * BPITCH + qW * 8] = make_uint2(h0, h1);
        *(uint2*)&sW[st][1][dW * BPITCH + qW * 8] = make_uint2(l0, l1);
        split_f4(wv1, h0, h1, l0, l1);
        *(uint2*)&sW[st][0][dW * BPITCH + qW * 8 + 4] = make_uint2(h0, h1);
        *(uint2*)&sW[st][1][dW * BPITCH + qW * 8 + 4] = make_uint2(l0, l1);
    };

    fill(0, 0);
    __syncthreads();

    for (int c = 0; c < 16; c++) {
        const int s = c & 1;
        if (c + 1 < 16) fill((c + 1) * 16, s ^ 1);

        uint32_t ah[4], al[4], bh[4][4], bl[4][4];
        ldsm4(ah, sm_addr(&sX[s][0][(m0w + rA) * BPITCH + cA]));
        ldsm4(al, sm_addr(&sX[s][1][(m0w + rA) * BPITCH + cA]));
        #pragma unroll
        for (int nq = 0; nq < 4; nq++) {
            ldsm4(bh[nq], sm_addr(&sW[s][0][(n0w + nq * 16 + rsel) * BPITCH + csel]));
            ldsm4(bl[nq], sm_addr(&sW[s][1][(n0w + nq * 16 + rsel) * BPITCH + csel]));
        }
        #pragma unroll
        for (int ni = 0; ni < 8; ni++) {
            const uint32_t* BH = &bh[ni >> 1][(ni & 1) * 2];
            const uint32_t* BL = &bl[ni >> 1][(ni & 1) * 2];
            hmma(acc[ni], ah, BH);
            hmma(acc[ni], ah, BL);
            hmma(acc[ni], al, BH);
        }
        __syncthreads();
    }

    // epilogue: bias + relu + store
    const int r = m0w + (lane >> 2);
    #pragma unroll
    for (int ni = 0; ni < 8; ni++) {
        int cix = n0w + ni * 8 + 2 * (lane & 3);
        float* O0 = out + (size_t)(gn0 + r) * D_ + cix;
        float* O1 = out + (size_t)(gn0 + r + 8) * D_ + cix;
        *(float2*)O0 = make_float2(fmaxf(acc[ni][0] + bb[ni].x, 0.f),
                                   fmaxf(acc[ni][1] + bb[ni].y, 0.f));
        *(float2*)O1 = make_float2(fmaxf(acc[ni][2] + bb[ni].x, 0.f),
                                   fmaxf(acc[ni][3] + bb[ni].y, 0.f));
    }
}

// ---------------------------------------------------------------------------
extern "C" void kernel_launch(void* const* d_in, const int* in_sizes, int n_in,
                              void* d_out, int out_size)
{
    const float *emb = nullptr, *cost = nullptr, *W = nullptr, *bias = nullptr;
    for (int i = 0; i < n_in; i++) {
        int s = in_sizes[i];
        if      (s == B_ * N_ * N_) cost = (const float*)d_in[i];
        else if (s == B_ * N_ * D_) emb  = (const float*)d_in[i];
        else if (s == 2 * D_ * D_)  W    = (const float*)d_in[i];
        else if (s == D_)           bias = (const float*)d_in[i];
    }

    prep2_kernel<<<dim3(N_ / 32, D_ / 32, B_), dim3(32, 8)>>>(emb);
    gemm1_mma_kernel<<<dim3(16, 8, 2), 256>>>(cost);
    gemm2_mma_kernel<<<256, 256>>>(emb, W, bias, (float*)d_out);
}

// round 12
// speedup vs baseline: 2.3341x; 1.1919x over previous
#include <cuda_runtime.h>
#include <cuda_fp16.h>
#include <cstdint>

#define B_ 8
#define N_ 2048
#define D_ 128
#define NCK 64                // gemm1 k-chunks per CTA (split-K=2: 64 x 16 = 1024)
#define SHALF (B_ * N_ * D_)
#define APITCH 136            // gemm1 A: halfs per k-row (128 j + pad) -> 272B
#define BPITCH 24             // gemm1 B / gemm2 W,X: halfs per row (16 k + pad) -> 48B

// ---------------------------------------------------------------------------
// Device scratch (no runtime allocation allowed)
// ---------------------------------------------------------------------------
__device__ float  g_S[2 * SHALF];       // two split-K partial sums (64 MB)
__device__ int    g_deg[B_ * N_];       // nnz per cost row
__device__ __half g_Bth[B_ * D_ * N_];  // emb transposed fp16: Bth[b][d][i] (16 MB)

// ---------------------------------------------------------------------------
// helpers
// ---------------------------------------------------------------------------
__device__ __forceinline__ void hmma(float* c, const uint32_t* a, const uint32_t* b) {
    asm volatile(
        "mma.sync.aligned.m16n8k16.row.col.f32.f16.f16.f32 "
        "{%0,%1,%2,%3}, {%4,%5,%6,%7}, {%8,%9}, {%0,%1,%2,%3};"
        : "+f"(c[0]), "+f"(c[1]), "+f"(c[2]), "+f"(c[3])
        : "r"(a[0]), "r"(a[1]), "r"(a[2]), "r"(a[3]), "r"(b[0]), "r"(b[1]));
}
__device__ __forceinline__ void ldsm4(uint32_t* r, uint32_t addr) {
    asm volatile("ldmatrix.sync.aligned.m8n8.x4.shared.b16 {%0,%1,%2,%3}, [%4];"
                 : "=r"(r[0]), "=r"(r[1]), "=r"(r[2]), "=r"(r[3]) : "r"(addr));
}
__device__ __forceinline__ void ldsm4t(uint32_t* r, uint32_t addr) {
    asm volatile("ldmatrix.sync.aligned.m8n8.x4.trans.shared.b16 {%0,%1,%2,%3}, [%4];"
                 : "=r"(r[0]), "=r"(r[1]), "=r"(r[2]), "=r"(r[3]) : "r"(addr));
}
__device__ __forceinline__ uint32_t sm_addr(const void* p) {
    return (uint32_t)__cvta_generic_to_shared(p);
}
// exact fp32 -> fp16 hi/lo split of a float4, packed as half2 words
__device__ __forceinline__ void split_f4(float4 v, uint32_t& h0, uint32_t& h1,
                                         uint32_t& l0, uint32_t& l1) {
    __half2 a = __floats2half2_rn(v.x, v.y);
    __half2 b = __floats2half2_rn(v.z, v.w);
    float2 af = __half22float2(a), bf = __half22float2(b);
    __half2 c = __floats2half2_rn(v.x - af.x, v.y - af.y);
    __half2 d = __floats2half2_rn(v.z - bf.x, v.w - bf.y);
    h0 = *(uint32_t*)&a; h1 = *(uint32_t*)&b;
    l0 = *(uint32_t*)&c; l1 = *(uint32_t*)&d;
}
// fp32 float4 -> fp16 (single rounding), packed as 2 half2 words
__device__ __forceinline__ void cvt_f4(float4 v, uint32_t& h0, uint32_t& h1) {
    __half2 a = __floats2half2_rn(v.x, v.y);
    __half2 b = __floats2half2_rn(v.z, v.w);
    h0 = *(uint32_t*)&a; h1 = *(uint32_t*)&b;
}

// ---------------------------------------------------------------------------
// prep2 (fused): transpose emb[b][i][d] -> fp16 g_Bth[b][d][i], zero g_deg
// ---------------------------------------------------------------------------
__global__ void prep2_kernel(const float* __restrict__ emb) {
    __shared__ float tile[32][33];
    int b = blockIdx.z;
    int i0 = blockIdx.x * 32;
    int d0 = blockIdx.y * 32;
    int tx = threadIdx.x, ty = threadIdx.y;   // (32, 8)
    int lbid = blockIdx.x + gridDim.x * (blockIdx.y + gridDim.y * blockIdx.z);
    int gid = lbid * 256 + ty * 32 + tx;
    if (gid < B_ * N_) g_deg[gid] = 0;

    const float* eB = emb + (size_t)b * N_ * D_;
    #pragma unroll
    for (int r = 0; r < 32; r += 8)
        tile[ty + r][tx] = eB[(size_t)(i0 + ty + r) * D_ + d0 + tx];
    __syncthreads();
    #pragma unroll
    for (int r = 0; r < 32; r += 8) {
        size_t o = (size_t)b * D_ * N_ + (size_t)(d0 + ty + r) * N_ + i0 + tx;
        g_Bth[o] = __float2half_rn(tile[tx][ty + r]);
    }
}

// ---------------------------------------------------------------------------
// gemm1 on mma.sync, single-term fp16 x fp16 (error ~1e-4 on S, diluted to
// ~2e-6 at the output by degree normalization + emb-dominated gemm2).
// C[j][d] += cost[k][j0+j] * Bth[d][k] over this CTA's K half (1024).
// CTA tile 128j x 128d, chunk 16, grid (16, 8, 2) = 256 CTAs -> 2 CTAs/SM.
// Chunk order: LDG(c+1) -> LDSM+MMA(c) -> cvt+STS(c+1) -> barrier, so the
// MMA section hides the DRAM latency (prefetch regs held across it).
// B loader: one d-row, 8 halfs (uint4, 16B) per thread -> full 128x16 tile.
// ---------------------------------------------------------------------------
__global__ __launch_bounds__(256, 2) void gemm1_mma_kernel(const float* __restrict__ cost)
{
    __shared__ __align__(16) __half sA[2][16 * APITCH];   // [stage][k][j]
    __shared__ __align__(16) __half sB[2][128 * BPITCH];  // [stage][d][k]

    const int tid = threadIdx.x, lane = tid & 31, w = tid >> 5;
    const int b = blockIdx.y, j0 = blockIdx.x * 128;
    const int kz = blockIdx.z, kbase = kz * (N_ / 2);
    const float* cB = cost + (size_t)b * N_ * N_;
    const __half* bT = g_Bth + (size_t)b * D_ * N_;

    // load-role indices
    const int kkA = w;                 // this warp loads cost rows kkA, kkA+8
    const int jq  = lane;
    const int dB  = tid >> 1;          // B row (0..127)
    const int kqB = (tid & 1) * 8;     // 8-half chunk within k16 (uint4)

    // mma-role indices: warp tile 32m x 64n
    const int wm = w & 3, wn = w >> 2;
    const int m0w = wm * 32, n0w = wn * 64;
    const int rsel = (lane & 7) + ((lane & 16) ? 8 : 0);
    const int csel = (lane & 8) ? 8 : 0;

    float acc[2][8][4];
    #pragma unroll
    for (int mi = 0; mi < 2; mi++)
        #pragma unroll
        for (int ni = 0; ni < 8; ni++)
            #pragma unroll
            for (int q = 0; q < 4; q++) acc[mi][ni][q] = 0.f;

    // ---- prologue: fill stage 0 with chunk 0 ----
    {
        const int i0 = kbase;
        float4 ca0 = *(const float4*)(cB + (size_t)(i0 + kkA) * N_ + j0 + jq * 4);
        float4 ca1 = *(const float4*)(cB + (size_t)(i0 + kkA + 8) * N_ + j0 + jq * 4);
        uint4  ebv = *(const uint4*)(bT + (size_t)dB * N_ + i0 + kqB);
        int c0 = (ca0.x != 0.f) + (ca0.y != 0.f) + (ca0.z != 0.f) + (ca0.w != 0.f);
        int c1 = (ca1.x != 0.f) + (ca1.y != 0.f) + (ca1.z != 0.f) + (ca1.w != 0.f);
        c0 = __reduce_add_sync(0xffffffffu, c0);
        c1 = __reduce_add_sync(0xffffffffu, c1);
        if (lane == 0) atomicAdd(&g_deg[b * N_ + i0 + kkA], c0);
        if (lane == 1) atomicAdd(&g_deg[b * N_ + i0 + kkA + 8], c1);

        uint32_t h0, h1;
        cvt_f4(ca0, h0, h1);
        *(uint2*)&sA[0][kkA * APITCH + jq * 4] = make_uint2(h0, h1);
        cvt_f4(ca1, h0, h1);
        *(uint2*)&sA[0][(kkA + 8) * APITCH + jq * 4] = make_uint2(h0, h1);
        *(uint4*)&sB[0][dB * BPITCH + kqB] = ebv;
    }
    __syncthreads();

    // ---- main loop ----
    for (int c = 0; c < NCK; c++) {
        const int s = c & 1;
        const bool more = (c + 1 < NCK);

        // 1) issue prefetch LDGs for chunk c+1 (held across the MMA section)
        float4 ca0, ca1; uint4 ebv;
        if (more) {
            const int i0 = kbase + (c + 1) * 16;
            ca0 = *(const float4*)(cB + (size_t)(i0 + kkA) * N_ + j0 + jq * 4);
            ca1 = *(const float4*)(cB + (size_t)(i0 + kkA + 8) * N_ + j0 + jq * 4);
            ebv = *(const uint4*)(bT + (size_t)dB * N_ + i0 + kqB);
        }

        // 2) consume stage s: 6 LDSM, 16 HMMA
        uint32_t ah[2][4], bh[4][4];
        #pragma unroll
        for (int mi = 0; mi < 2; mi++)
            ldsm4t(ah[mi], sm_addr(&sA[s][rsel * APITCH + m0w + mi * 16 + csel]));
        #pragma unroll
        for (int nq = 0; nq < 4; nq++)
            ldsm4(bh[nq], sm_addr(&sB[s][(n0w + nq * 16 + rsel) * BPITCH + csel]));
        #pragma unroll
        for (int mi = 0; mi < 2; mi++)
            #pragma unroll
            for (int ni = 0; ni < 8; ni++)
                hmma(acc[mi][ni], ah[mi], &bh[ni >> 1][(ni & 1) * 2]);

        // 3) degree + convert + store chunk c+1 into stage s^1
        if (more) {
            const int i0 = kbase + (c + 1) * 16;
            const int ns = s ^ 1;
            int c0 = (ca0.x != 0.f) + (ca0.y != 0.f) + (ca0.z != 0.f) + (ca0.w != 0.f);
            int c1 = (ca1.x != 0.f) + (ca1.y != 0.f) + (ca1.z != 0.f) + (ca1.w != 0.f);
            c0 = __reduce_add_sync(0xffffffffu, c0);
            c1 = __reduce_add_sync(0xffffffffu, c1);
            if (lane == 0) atomicAdd(&g_deg[b * N_ + i0 + kkA], c0);
            if (lane == 1) atomicAdd(&g_deg[b * N_ + i0 + kkA + 8], c1);

            uint32_t h0, h1;
            cvt_f4(ca0, h0, h1);
            *(uint2*)&sA[ns][kkA * APITCH + jq * 4] = make_uint2(h0, h1);
            cvt_f4(ca1, h0, h1);
            *(uint2*)&sA[ns][(kkA + 8) * APITCH + jq * 4] = make_uint2(h0, h1);
            *(uint4*)&sB[ns][dB * BPITCH + kqB] = ebv;
        }
        __syncthreads();
    }

    // ---- epilogue: fragments -> g_S[kz][b][j][d] ----
    float* Sr = g_S + (size_t)kz * SHALF + ((size_t)(b * N_ + j0)) * D_;
    #pragma unroll
    for (int mi = 0; mi < 2; mi++) {
        int r = m0w + mi * 16 + (lane >> 2);
        #pragma unroll
        for (int ni = 0; ni < 8; ni++) {
            int cix = n0w + ni * 8 + 2 * (lane & 3);
            *(float2*)(Sr + (size_t)r * D_ + cix)       = make_float2(acc[mi][ni][0], acc[mi][ni][1]);
            *(float2*)(Sr + (size_t)(r + 8) * D_ + cix) = make_float2(acc[mi][ni][2], acc[mi][ni][3]);
        }
    }
}

// ---------------------------------------------------------------------------
// gemm2 on mma.sync fp16 hi/lo split (3 terms):
//   out[n,d] = relu( sum_f X[n,f] * W[d,f] + bias[d] )
//   X[n,f] = (f < 128) ? emb[n,f] : (S0[n,f-128]+S1[n,f-128]) / degree[n]
// CTA tile 64n x 128d, K = 256 in 16 chunks, grid 256, 256 threads.
// ---------------------------------------------------------------------------
__global__ __launch_bounds__(256, 2) void gemm2_mma_kernel(
    const float* __restrict__ emb, const float* __restrict__ W,
    const float* __restrict__ bias, float* __restrict__ out)
{
    __shared__ __align__(16) __half sX[2][2][64 * BPITCH];    // [stage][hi/lo][n][f]
    __shared__ __align__(16) __half sW[2][2][128 * BPITCH];   // [stage][hi/lo][d][f]

    const int tid = threadIdx.x, lane = tid & 31, w = tid >> 5;
    const int gn0 = blockIdx.x * 64;

    // producer roles
    const int nX = tid >> 2, fqX = (tid & 3) * 4;   // X: row nX, f-quad fqX
    const int dW = tid & 127, qW = tid >> 7;        // W: row dW, 8-f half qW
    const float invdeg = 1.0f / (float)g_deg[gn0 + nX];

    // mma roles: warp tile 16m x 64n; 4 m-slots x 2 n-slots
    const int wm = w & 3, wn = w >> 2;
    const int m0w = wm * 16, n0w = wn * 64;
    const int rA = lane & 15, cA = (lane & 16) ? 8 : 0;          // A row-major map
    const int rsel = (lane & 7) + ((lane & 16) ? 8 : 0);         // B map (proven)
    const int csel = (lane & 8) ? 8 : 0;

    float acc[8][4];
    #pragma unroll
    for (int ni = 0; ni < 8; ni++)
        #pragma unroll
        for (int q = 0; q < 4; q++) acc[ni][q] = 0.f;

    // bias preload (per-thread columns)
    float2 bb[8];
    #pragma unroll
    for (int ni = 0; ni < 8; ni++) {
        int cix = n0w + ni * 8 + 2 * (lane & 3);
        bb[ni] = make_float2(bias[cix], bias[cix + 1]);
    }

    // producer: fill stage st with f-chunk k0
    auto fill = [&](int k0, int st) {
        float4 xv;
        if (k0 < D_) {
            xv = *(const float4*)(emb + (size_t)(gn0 + nX) * D_ + k0 + fqX);
        } else {
            const float* s0p = g_S + (size_t)(gn0 + nX) * D_ + (k0 - D_) + fqX;
            float4 a = *(const float4*)s0p;
            float4 bq = *(const float4*)(s0p + SHALF);
            xv = make_float4((a.x + bq.x) * invdeg, (a.y + bq.y) * invdeg,
                             (a.z + bq.z) * invdeg, (a.w + bq.w) * invdeg);
        }
        float4 wv0 = *(const float4*)(W + (size_t)dW * 256 + k0 + qW * 8);
        float4 wv1 = *(const float4*)(W + (size_t)dW * 256 + k0 + qW * 8 + 4);

        uint32_t h0, h1, l0, l1;
        split_f4(xv, h0, h1, l0, l1);
        *(uint2*)&sX[st][0][nX * BPITCH + fqX] = make_uint2(h0, h1);
        *(uint2*)&sX[st][1][nX * BPITCH + fqX] = make_uint2(l0, l1);
        split_f4(wv0, h0, h1, l0, l1);
        *(uint2*)&sW[st][0][dW * BPITCH + qW * 8] = make_uint2(h0, h1);
        *(uint2*)&sW[st][1][dW * BPITCH + qW * 8] = make_uint2(l0, l1);
        split_f4(wv1, h0, h1, l0, l1);
        *(uint2*)&sW[st][0][dW * BPITCH + qW * 8 + 4] = make_uint2(h0, h1);
        *(uint2*)&sW[st][1][dW * BPITCH + qW * 8 + 4] = make_uint2(l0, l1);
    };

    fill(0, 0);
    __syncthreads();

    for (int c = 0; c < 16; c++) {
        const int s = c & 1;
        if (c + 1 < 16) fill((c + 1) * 16, s ^ 1);

        uint32_t ah[4], al[4], bh[4][4], bl[4][4];
        ldsm4(ah, sm_addr(&sX[s][0][(m0w + rA) * BPITCH + cA]));
        ldsm4(al, sm_addr(&sX[s][1][(m0w + rA) * BPITCH + cA]));
        #pragma unroll
        for (int nq = 0; nq < 4; nq++) {
            ldsm4(bh[nq], sm_addr(&sW[s][0][(n0w + nq * 16 + rsel) * BPITCH + csel]));
            ldsm4(bl[nq], sm_addr(&sW[s][1][(n0w + nq * 16 + rsel) * BPITCH + csel]));
        }
        #pragma unroll
        for (int ni = 0; ni < 8; ni++) {
            const uint32_t* BH = &bh[ni >> 1][(ni & 1) * 2];
            const uint32_t* BL = &bl[ni >> 1][(ni & 1) * 2];
            hmma(acc[ni], ah, BH);
            hmma(acc[ni], ah, BL);
            hmma(acc[ni], al, BH);
        }
        __syncthreads();
    }

    // epilogue: bias + relu + store
    const int r = m0w + (lane >> 2);
    #pragma unroll
    for (int ni = 0; ni < 8; ni++) {
        int cix = n0w + ni * 8 + 2 * (lane & 3);
        float* O0 = out + (size_t)(gn0 + r) * D_ + cix;
        float* O1 = out + (size_t)(gn0 + r + 8) * D_ + cix;
        *(float2*)O0 = make_float2(fmaxf(acc[ni][0] + bb[ni].x, 0.f),
                                   fmaxf(acc[ni][1] + bb[ni].y, 0.f));
        *(float2*)O1 = make_float2(fmaxf(acc[ni][2] + bb[ni].x, 0.f),
                                   fmaxf(acc[ni][3] + bb[ni].y, 0.f));
    }
}

// ---------------------------------------------------------------------------
extern "C" void kernel_launch(void* const* d_in, const int* in_sizes, int n_in,
                              void* d_out, int out_size)
{
    const float *emb = nullptr, *cost = nullptr, *W = nullptr, *bias = nullptr;
    for (int i = 0; i < n_in; i++) {
        int s = in_sizes[i];
        if      (s == B_ * N_ * N_) cost = (const float*)d_in[i];
        else if (s == B_ * N_ * D_) emb  = (const float*)d_in[i];
        else if (s == 2 * D_ * D_)  W    = (const float*)d_in[i];
        else if (s == D_)           bias = (const float*)d_in[i];
    }

    prep2_kernel<<<dim3(N_ / 32, D_ / 32, B_), dim3(32, 8)>>>(emb);
    gemm1_mma_kernel<<<dim3(16, 8, 2), 256>>>(cost);
    gemm2_mma_kernel<<<256, 256>>>(emb, W, bias, (float*)d_out);
}